// round 1
// baseline (speedup 1.0000x reference)
#include <cuda_runtime.h>
#include <cstdint>

// Winograd F(2x2,3x3): N=16, C=128, O=128, H=W=112, pad=1
#define NB 16
#define CD 128
#define OD 128
#define HH 112
#define NT 56
#define TPI (NT*NT)            // 3136 tiles per image
#define TILES (NB*TPI)         // 50176 total tiles
#define PST ((size_t)CD*TILES) // 6422528 per-position plane stride (C*TILES == O*TILES)

// Scratch: __device__ globals (allocation-free kernel_launch per harness rules)
__device__ float g_U[16 * CD * OD];     //  1 MB  U[p][c][o]  (k-major for GEMM A)
__device__ float g_V[102760448];        // 411 MB V[p][c][tile]
__device__ float g_M[102760448];        // 411 MB M[p][o][tile]

// ---------------- packed f32x2 helpers (FFMA2 path, ptxas won't auto-emit) ----
__device__ __forceinline__ unsigned long long dup2(float a) {
    unsigned long long r;
    unsigned int ai = __float_as_uint(a);
    asm("mov.b64 %0, {%1, %1};" : "=l"(r) : "r"(ai));
    return r;
}
__device__ __forceinline__ void ffma2(unsigned long long& d,
                                      unsigned long long a,
                                      unsigned long long b) {
    asm("fma.rn.f32x2 %0, %1, %2, %0;" : "+l"(d) : "l"(a), "l"(b));
}

// ---------------- K1: weight transform  U = G g G^T,  layout U[p][c][o] -------
__global__ void k_wt(const float* __restrict__ w) {
    int tid = blockIdx.x * 128 + threadIdx.x;   // 16384 threads
    int o = tid & 127;
    int c = tid >> 7;
    const float* g = w + ((size_t)o * CD + c) * 9;
    float gm[3][3];
#pragma unroll
    for (int i = 0; i < 3; i++)
#pragma unroll
        for (int j = 0; j < 3; j++) gm[i][j] = g[i * 3 + j];

    float t[4][3];
#pragma unroll
    for (int k = 0; k < 3; k++) {
        t[0][k] = gm[0][k];
        t[1][k] = 0.5f * (gm[0][k] + gm[1][k] + gm[2][k]);
        t[2][k] = 0.5f * (gm[0][k] - gm[1][k] + gm[2][k]);
        t[3][k] = gm[2][k];
    }
#pragma unroll
    for (int i = 0; i < 4; i++) {
        float u0 = t[i][0];
        float u1 = 0.5f * (t[i][0] + t[i][1] + t[i][2]);
        float u2 = 0.5f * (t[i][0] - t[i][1] + t[i][2]);
        float u3 = t[i][2];
        g_U[(i * 4 + 0) * (CD * OD) + c * OD + o] = u0;
        g_U[(i * 4 + 1) * (CD * OD) + c * OD + o] = u1;
        g_U[(i * 4 + 2) * (CD * OD) + c * OD + o] = u2;
        g_U[(i * 4 + 3) * (CD * OD) + c * OD + o] = u3;
    }
}

// ---------------- K2: input transform  V = BT d BT^T ---------------------------
__global__ void k_in(const float* __restrict__ x) {
    int gid = blockIdx.x * 256 + threadIdx.x;   // CD*TILES = 6,422,528
    int c = gid / TILES;
    int tile = gid - c * TILES;
    int n = tile / TPI;
    int r = tile - n * TPI;
    int ty = r / NT;
    int tx = r - ty * NT;

    const float* xp = x + ((size_t)(n * CD + c)) * (HH * HH);
    int r0 = 2 * ty - 1, c0 = 2 * tx - 1;

    float d[4][4];
#pragma unroll
    for (int ii = 0; ii < 4; ii++) {
        int rr = r0 + ii;
        bool okr = ((unsigned)rr < HH);
#pragma unroll
        for (int jj = 0; jj < 4; jj++) {
            int cc = c0 + jj;
            d[ii][jj] = (okr && (unsigned)cc < HH) ? xp[rr * HH + cc] : 0.0f;
        }
    }
    float t[4][4];
#pragma unroll
    for (int j = 0; j < 4; j++) {
        t[0][j] = d[0][j] - d[2][j];
        t[1][j] = d[1][j] + d[2][j];
        t[2][j] = d[2][j] - d[1][j];
        t[3][j] = d[1][j] - d[3][j];
    }
    size_t base = (size_t)c * TILES + tile;
#pragma unroll
    for (int i = 0; i < 4; i++) {
        float v0 = t[i][0] - t[i][2];
        float v1 = t[i][1] + t[i][2];
        float v2 = t[i][2] - t[i][1];
        float v3 = t[i][1] - t[i][3];
        g_V[(size_t)(i * 4 + 0) * PST + base] = v0;
        g_V[(size_t)(i * 4 + 1) * PST + base] = v1;
        g_V[(size_t)(i * 4 + 2) * PST + base] = v2;
        g_V[(size_t)(i * 4 + 3) * PST + base] = v3;
    }
}

// ---------------- K3: 16x batched SGEMM  M[p] = U[p]^T-free (A already k-major) -
// A = U[p] : [c][o] 128x128 (whole tile resident in SMEM)
// B = V[p] : [c][tile], C = M[p] : [o][tile]
// 256 threads, BM=128, BN=128, BK=16 double-buffered, 8x8 micro-tile via f32x2
#define GEMM_SMEM ((128 * 128 + 2 * 16 * 128) * 4)   // 81920 B

__global__ void __launch_bounds__(256, 2) k_gemm() {
    extern __shared__ float sm[];
    float* As = sm;                 // [c][o] 128x128
    float* Bs = sm + 128 * 128;     // 2 x [16][128]

    const int p = blockIdx.y;
    const int jb = blockIdx.x * 128;
    const float* __restrict__ A = g_U + p * (CD * OD);
    const float* __restrict__ B = g_V + (size_t)p * PST;
    float* __restrict__ Cm = g_M + (size_t)p * PST;
    const int tid = threadIdx.x;

    // Stage all of A (64 KB) — straight float4 copy, conflict-free
    {
        const float4* A4 = (const float4*)A;
        float4* As4 = (float4*)As;
#pragma unroll
        for (int i = 0; i < 16; i++) As4[i * 256 + tid] = A4[i * 256 + tid];
    }

    // Prefetch B chunk 0 (16x128 floats, 2 float4 per thread)
    float4 rb0, rb1;
    {
        int l0 = tid, l1 = 256 + tid;
        rb0 = *(const float4*)&B[(size_t)(l0 >> 5) * TILES + jb + 4 * (l0 & 31)];
        rb1 = *(const float4*)&B[(size_t)(l1 >> 5) * TILES + jb + 4 * (l1 & 31)];
        *(float4*)&Bs[(l0 >> 5) * 128 + 4 * (l0 & 31)] = rb0;
        *(float4*)&Bs[(l1 >> 5) * 128 + 4 * (l1 & 31)] = rb1;
    }
    __syncthreads();

    unsigned long long acc[8][4];
#pragma unroll
    for (int i = 0; i < 8; i++)
#pragma unroll
        for (int j = 0; j < 4; j++) acc[i][j] = 0ULL;

    const int row0 = (tid >> 4) * 8;          // o rows
    const int tx4 = (tid & 15) * 4;           // j columns: [4t..4t+3] and [64+4t..]

    for (int ch = 0; ch < 8; ch++) {
        if (ch < 7) {   // issue next chunk's global loads; latency hidden by compute
            int kc = (ch + 1) * 16;
            int l0 = tid, l1 = 256 + tid;
            rb0 = *(const float4*)&B[(size_t)(kc + (l0 >> 5)) * TILES + jb + 4 * (l0 & 31)];
            rb1 = *(const float4*)&B[(size_t)(kc + (l1 >> 5)) * TILES + jb + 4 * (l1 & 31)];
        }
        const float* bsc = Bs + (ch & 1) * (16 * 128);
#pragma unroll
        for (int kk = 0; kk < 16; kk++) {
            int k = ch * 16 + kk;
            float4 a0 = *(const float4*)&As[k * 128 + row0];
            float4 a1 = *(const float4*)&As[k * 128 + row0 + 4];
            ulonglong2 b01 = *(const ulonglong2*)&bsc[kk * 128 + tx4];
            ulonglong2 b23 = *(const ulonglong2*)&bsc[kk * 128 + 64 + tx4];
            float av[8] = {a0.x, a0.y, a0.z, a0.w, a1.x, a1.y, a1.z, a1.w};
#pragma unroll
            for (int i = 0; i < 8; i++) {
                unsigned long long ad = dup2(av[i]);
                ffma2(acc[i][0], ad, b01.x);
                ffma2(acc[i][1], ad, b01.y);
                ffma2(acc[i][2], ad, b23.x);
                ffma2(acc[i][3], ad, b23.y);
            }
        }
        if (ch < 7) {
            float* bsn = Bs + ((ch + 1) & 1) * (16 * 128);
            int l0 = tid, l1 = 256 + tid;
            *(float4*)&bsn[(l0 >> 5) * 128 + 4 * (l0 & 31)] = rb0;
            *(float4*)&bsn[(l1 >> 5) * 128 + 4 * (l1 & 31)] = rb1;
        }
        __syncthreads();
    }

    // Epilogue: pair accumulators are (j, j+1) adjacent → direct float4 stores
#pragma unroll
    for (int i = 0; i < 8; i++) {
        union { unsigned long long u[2]; float4 f; } lo, hi;
        lo.u[0] = acc[i][0]; lo.u[1] = acc[i][1];
        hi.u[0] = acc[i][2]; hi.u[1] = acc[i][3];
        size_t base = (size_t)(row0 + i) * TILES + jb;
        *(float4*)&Cm[base + tx4] = lo.f;
        *(float4*)&Cm[base + 64 + tx4] = hi.f;
    }
}

// ---------------- K4: output transform  Y = AT M AT^T + bias -------------------
__global__ void k_out(const float* __restrict__ bias, float* __restrict__ y) {
    int gid = blockIdx.x * 256 + threadIdx.x;   // OD*TILES
    int o = gid / TILES;
    int tile = gid - o * TILES;
    int n = tile / TPI;
    int r = tile - n * TPI;
    int ty = r / NT;
    int tx = r - ty * NT;

    float m[16];
#pragma unroll
    for (int p = 0; p < 16; p++) m[p] = g_M[(size_t)p * PST + gid];

    float b = bias[o];
    float r0[4], r1[4];
#pragma unroll
    for (int j = 0; j < 4; j++) {
        r0[j] = m[j] + m[4 + j] + m[8 + j];
        r1[j] = m[4 + j] - m[8 + j] - m[12 + j];
    }
    float y00 = r0[0] + r0[1] + r0[2] + b;
    float y01 = r0[1] - r0[2] - r0[3] + b;
    float y10 = r1[0] + r1[1] + r1[2] + b;
    float y11 = r1[1] - r1[2] - r1[3] + b;

    float* yp = y + ((size_t)(n * OD + o) * HH + 2 * ty) * HH + 2 * tx;
    yp[0] = y00;
    yp[1] = y01;
    yp[HH] = y10;
    yp[HH + 1] = y11;
}

// ---------------- launch --------------------------------------------------------
extern "C" void kernel_launch(void* const* d_in, const int* in_sizes, int n_in,
                              void* d_out, int out_size) {
    const float* x = (const float*)d_in[0];
    const float* w = (const float*)d_in[1];
    const float* bias = (const float*)d_in[2];
    float* y = (float*)d_out;

    cudaFuncSetAttribute(k_gemm, cudaFuncAttributeMaxDynamicSharedMemorySize, GEMM_SMEM);

    k_wt<<<128, 128>>>(w);
    k_in<<<(CD * TILES) / 256, 256>>>(x);
    dim3 gg(TILES / 128, 16);               // 392 x 16
    k_gemm<<<gg, 256, GEMM_SMEM>>>();
    k_out<<<(OD * TILES) / 256, 256>>>(bias, y);
}

// round 3
// speedup vs baseline: 1.2414x; 1.2414x over previous
#include <cuda_runtime.h>
#include <cuda_bf16.h>
#include <cstdint>

// Winograd F(2x2,3x3): N=16, C=128, O=128, H=W=112, pad=1
#define NB 16
#define CD 128
#define OD 128
#define HH 112
#define NT 56
#define TPI (NT*NT)            // 3136 tiles per image
#define TILES (NB*TPI)         // 50176 total tiles
#define PST ((size_t)OD*TILES) // per-position M plane stride

// Scratch (allocation-free kernel_launch): U/V as bf16 hi|lo, M fp32
__device__ unsigned short g_Ub[16 * OD * 256];            //  1 MB  U[p][o][c_hi(128)|c_lo(128)]
__device__ unsigned short g_Vb[(size_t)16 * TILES * 256]; // 411 MB V[p][tile][c_hi|c_lo]
__device__ float g_M[(size_t)16 * OD * TILES];            // 411 MB M[p][o][tile]

__device__ __forceinline__ uint32_t smem_to_u32(const void* p) {
    uint32_t a;
    asm("{ .reg .u64 t; cvta.to.shared.u64 t, %1; cvt.u32.u64 %0, t; }" : "=r"(a) : "l"(p));
    return a;
}

// ldmatrix x4 (sm_75+, no arch-'a' gating)
#define LDSM4(r, addr) \
    asm volatile("ldmatrix.sync.aligned.m8n8.x4.shared.b16 {%0,%1,%2,%3}, [%4];" \
        : "=r"((r)[0]), "=r"((r)[1]), "=r"((r)[2]), "=r"((r)[3]) : "r"(addr))

// bf16 HMMA (sm_80+, no arch-'a' gating)
#define MMA_BF16(d, a, b) \
    asm volatile("mma.sync.aligned.m16n8k16.row.col.f32.bf16.bf16.f32 " \
        "{%0,%1,%2,%3},{%4,%5,%6,%7},{%8,%9},{%0,%1,%2,%3};" \
        : "+f"((d)[0]), "+f"((d)[1]), "+f"((d)[2]), "+f"((d)[3]) \
        : "r"((a)[0]), "r"((a)[1]), "r"((a)[2]), "r"((a)[3]), \
          "r"((b)[0]), "r"((b)[1]))

__device__ __forceinline__ uint32_t split_pack(float v) {
    __nv_bfloat16 h = __float2bfloat16(v);
    float hf = __bfloat162float(h);
    __nv_bfloat16 l = __float2bfloat16(v - hf);
    uint16_t hu = __bfloat16_as_ushort(h);
    uint16_t lu = __bfloat16_as_ushort(l);
    return (uint32_t)hu | ((uint32_t)lu << 16);
}

// SMEM 512B-row swizzle: 32x 16B units/row; phys unit keeps bits[4:3], XORs low3 with row
__device__ __forceinline__ uint32_t swz(uint32_t u, uint32_t row) {
    return (u & 24u) | ((u ^ row) & 7u);
}

// ---------------- K1: weight transform  U = G g G^T -> bf16 hi|lo ------------
__global__ void k_wt(const float* __restrict__ w) {
    int tid = blockIdx.x * 128 + threadIdx.x;   // 16384 threads: (c,o)
    int o = tid & 127;
    int c = tid >> 7;
    const float* g = w + ((size_t)o * CD + c) * 9;
    float gm[3][3];
#pragma unroll
    for (int i = 0; i < 3; i++)
#pragma unroll
        for (int j = 0; j < 3; j++) gm[i][j] = g[i * 3 + j];

    float t[4][3];
#pragma unroll
    for (int k = 0; k < 3; k++) {
        t[0][k] = gm[0][k];
        t[1][k] = 0.5f * (gm[0][k] + gm[1][k] + gm[2][k]);
        t[2][k] = 0.5f * (gm[0][k] - gm[1][k] + gm[2][k]);
        t[3][k] = gm[2][k];
    }
#pragma unroll
    for (int i = 0; i < 4; i++) {
        float u[4];
        u[0] = t[i][0];
        u[1] = 0.5f * (t[i][0] + t[i][1] + t[i][2]);
        u[2] = 0.5f * (t[i][0] - t[i][1] + t[i][2]);
        u[3] = t[i][2];
#pragma unroll
        for (int j = 0; j < 4; j++) {
            int p = i * 4 + j;
            uint32_t hl = split_pack(u[j]);
            unsigned short* up = g_Ub + ((size_t)(p * OD + o)) * 256;
            up[c] = (unsigned short)(hl & 0xffff);
            up[128 + c] = (unsigned short)(hl >> 16);
        }
    }
}

// ---------------- K2: input transform -> V[p][tile][c_hi|c_lo] bf16 ----------
__global__ void __launch_bounds__(256) k_in(const float* __restrict__ x) {
    extern __shared__ uint32_t S[];   // [32 c][16 p][32 tiles] = 64KB
    const int tid = threadIdx.x;
    const int lane = tid & 31;
    const int cg8 = tid >> 5;

    {
        int tile = blockIdx.x * 32 + lane;
        int n = tile / TPI;
        int r = tile - n * TPI;
        int ty = r / NT;
        int tx = r - ty * NT;
        int r0 = 2 * ty - 1, c0 = 2 * tx - 1;
        const float* xn = x + (size_t)n * CD * (HH * HH);

#pragma unroll
        for (int cs = 0; cs < 4; cs++) {
            int cl = cg8 * 4 + cs;                 // local c 0..31
            int c = blockIdx.y * 32 + cl;
            const float* xp = xn + (size_t)c * (HH * HH);
            float d[4][4];
#pragma unroll
            for (int ii = 0; ii < 4; ii++) {
                int rr = r0 + ii;
                bool okr = ((unsigned)rr < HH);
#pragma unroll
                for (int jj = 0; jj < 4; jj++) {
                    int cc = c0 + jj;
                    d[ii][jj] = (okr && (unsigned)cc < HH) ? xp[rr * HH + cc] : 0.0f;
                }
            }
            float t[4][4];
#pragma unroll
            for (int j = 0; j < 4; j++) {
                t[0][j] = d[0][j] - d[2][j];
                t[1][j] = d[1][j] + d[2][j];
                t[2][j] = d[2][j] - d[1][j];
                t[3][j] = d[1][j] - d[3][j];
            }
#pragma unroll
            for (int i = 0; i < 4; i++) {
                float v0 = t[i][0] - t[i][2];
                float v1 = t[i][1] + t[i][2];
                float v2 = t[i][2] - t[i][1];
                float v3 = t[i][1] - t[i][3];
                S[(cl * 16 + (i * 4 + 0)) * 32 + lane] = split_pack(v0);
                S[(cl * 16 + (i * 4 + 1)) * 32 + lane] = split_pack(v1);
                S[(cl * 16 + (i * 4 + 2)) * 32 + lane] = split_pack(v2);
                S[(cl * 16 + (i * 4 + 3)) * 32 + lane] = split_pack(v3);
            }
        }
    }
    __syncthreads();

    // Pass 2: each thread emits one (p, tile) 32-channel chunk: 64B hi + 64B lo
#pragma unroll
    for (int it = 0; it < 2; it++) {
        int q = it * 256 + tid;      // 512 = 16p * 32tiles
        int p = q >> 5;
        int tl = q & 31;
        int tile = blockIdx.x * 32 + tl;

        uint32_t hp[16], lp[16];
#pragma unroll
        for (int c2 = 0; c2 < 16; c2++) {
            uint32_t u0 = S[((2 * c2) * 16 + p) * 32 + tl];
            uint32_t u1 = S[((2 * c2 + 1) * 16 + p) * 32 + tl];
            hp[c2] = (u0 & 0xffffu) | (u1 << 16);
            lp[c2] = (u0 >> 16) | (u1 & 0xffff0000u);
        }
        unsigned short* vb = g_Vb + ((size_t)p * TILES + tile) * 256 + blockIdx.y * 32;
#pragma unroll
        for (int i = 0; i < 4; i++) {
            *(uint4*)(vb + i * 8) = *((uint4*)hp + i);
            *(uint4*)(vb + 128 + i * 8) = *((uint4*)lp + i);
        }
    }
}

// ---------------- K3: HMMA GEMM  M[p] = U[p] V[p]  (bf16 3-split) -------------
// CTA: 128(o) x 64(tiles), K=128 resident. A 64KB + B 32KB swizzled SMEM.
// D = Ah*Bh + Ah*Bl + Al*Bh  (fp32 accum)
#define GEMM_SMEM (64 * 1024 + 32 * 1024)

__global__ void __launch_bounds__(256, 2) k_gemm() {
    extern __shared__ char sm[];
    const uint32_t aBase = smem_to_u32(sm);
    const uint32_t bBase = aBase + 65536;
    const int tid = threadIdx.x;
    const int p = blockIdx.y;
    const int jb = blockIdx.x * 64;

    // Stage A: U[p] 128 rows x 32 units(16B) each (hi units 0-15 | lo 16-31)
    {
        const uint4* gA = (const uint4*)(g_Ub + (size_t)p * OD * 256);
#pragma unroll
        for (int i = 0; i < 16; i++) {
            int g = i * 256 + tid;
            uint32_t row = (uint32_t)g >> 5, u = (uint32_t)g & 31;
            uint4 v = gA[g];
            *(uint4*)(sm + row * 512 + swz(u, row) * 16) = v;
        }
    }
    // Stage B: V[p][jb..jb+63] 64 rows x 32 units
    {
        const uint4* gB = (const uint4*)(g_Vb + ((size_t)p * TILES + jb) * 256);
#pragma unroll
        for (int i = 0; i < 8; i++) {
            int g = i * 256 + tid;
            uint32_t row = (uint32_t)g >> 5, u = (uint32_t)g & 31;
            uint4 v = gB[g];
            *(uint4*)(sm + 65536 + row * 512 + swz(u, row) * 16) = v;
        }
    }
    __syncthreads();

    const int wid = tid >> 5;
    const int lane = tid & 31;
    const int o0 = (wid & 3) * 32;   // warp M block
    const int n0 = (wid >> 2) * 32;  // warp N block

    float acc[2][4][4];
#pragma unroll
    for (int m = 0; m < 2; m++)
#pragma unroll
        for (int nf = 0; nf < 4; nf++)
#pragma unroll
            for (int r = 0; r < 4; r++) acc[m][nf][r] = 0.0f;

    // ldmatrix lane geometry
    const uint32_t rA = (uint32_t)(o0 + (lane & 15));            // +16 for m=1
    const uint32_t uA = (uint32_t)(lane >> 4);                   // 0/1 -> k lo/hi half
    const uint32_t rB = (uint32_t)(n0 + (lane & 7) + ((lane & 16) >> 1)); // +16 for q=1
    const uint32_t uB = (uint32_t)((lane >> 3) & 1);

#pragma unroll
    for (int kc = 0; kc < 8; kc++) {
        uint32_t ah[2][4], al[2][4], bh[4][2], bl[4][2];
#pragma unroll
        for (int m = 0; m < 2; m++) {
            uint32_t r = rA + m * 16;
            uint32_t u = 2 * kc + uA;                    // hi split units
            LDSM4(ah[m], aBase + r * 512 + (swz(u, r) << 4));
            u += 16;                                     // lo split units
            LDSM4(al[m], aBase + r * 512 + (swz(u, r) << 4));
        }
#pragma unroll
        for (int q = 0; q < 2; q++) {
            uint32_t r = rB + q * 16;
            uint32_t u = 2 * kc + uB;
            uint32_t t[4];
            LDSM4(t, bBase + r * 512 + (swz(u, r) << 4));
            bh[2 * q][0] = t[0]; bh[2 * q][1] = t[1];
            bh[2 * q + 1][0] = t[2]; bh[2 * q + 1][1] = t[3];
            u += 16;
            LDSM4(t, bBase + r * 512 + (swz(u, r) << 4));
            bl[2 * q][0] = t[0]; bl[2 * q][1] = t[1];
            bl[2 * q + 1][0] = t[2]; bl[2 * q + 1][1] = t[3];
        }
#pragma unroll
        for (int m = 0; m < 2; m++)
#pragma unroll
            for (int nf = 0; nf < 4; nf++) {
                MMA_BF16(acc[m][nf], ah[m], bh[nf]);
                MMA_BF16(acc[m][nf], ah[m], bl[nf]);
                MMA_BF16(acc[m][nf], al[m], bh[nf]);
            }
    }

    // Epilogue: D row = o, col = tile; thread (t): rows o0+m*16+t/4 (+8), cols n0+nf*8+(t%4)*2
    float* outp = g_M + (size_t)p * PST + jb;
#pragma unroll
    for (int m = 0; m < 2; m++) {
        int ro = o0 + m * 16 + (lane >> 2);
#pragma unroll
        for (int nf = 0; nf < 4; nf++) {
            int col = n0 + nf * 8 + (lane & 3) * 2;
            float2 v0 = make_float2(acc[m][nf][0], acc[m][nf][1]);
            float2 v1 = make_float2(acc[m][nf][2], acc[m][nf][3]);
            *(float2*)(outp + (size_t)ro * TILES + col) = v0;
            *(float2*)(outp + (size_t)(ro + 8) * TILES + col) = v1;
        }
    }
}

// ---------------- K4: output transform  Y = AT M AT^T + bias ------------------
__global__ void k_out(const float* __restrict__ bias, float* __restrict__ y) {
    int gid = blockIdx.x * 256 + threadIdx.x;   // OD*TILES
    int o = gid / TILES;
    int tile = gid - o * TILES;
    int n = tile / TPI;
    int r = tile - n * TPI;
    int ty = r / NT;
    int tx = r - ty * NT;

    float m[16];
#pragma unroll
    for (int p = 0; p < 16; p++) m[p] = g_M[(size_t)p * PST + gid];

    float b = bias[o];
    float r0[4], r1[4];
#pragma unroll
    for (int j = 0; j < 4; j++) {
        r0[j] = m[j] + m[4 + j] + m[8 + j];
        r1[j] = m[4 + j] - m[8 + j] - m[12 + j];
    }
    float y00 = r0[0] + r0[1] + r0[2] + b;
    float y01 = r0[1] - r0[2] - r0[3] + b;
    float y10 = r1[0] + r1[1] + r1[2] + b;
    float y11 = r1[1] - r1[2] - r1[3] + b;

    float* yp = y + ((size_t)(n * OD + o) * HH + 2 * ty) * HH + 2 * tx;
    yp[0] = y00;
    yp[1] = y01;
    yp[HH] = y10;
    yp[HH + 1] = y11;
}

// ---------------- launch --------------------------------------------------------
extern "C" void kernel_launch(void* const* d_in, const int* in_sizes, int n_in,
                              void* d_out, int out_size) {
    const float* x = (const float*)d_in[0];
    const float* w = (const float*)d_in[1];
    const float* bias = (const float*)d_in[2];
    float* y = (float*)d_out;

    cudaFuncSetAttribute(k_in, cudaFuncAttributeMaxDynamicSharedMemorySize, 65536);
    cudaFuncSetAttribute(k_gemm, cudaFuncAttributeMaxDynamicSharedMemorySize, GEMM_SMEM);

    k_wt<<<128, 128>>>(w);
    dim3 gi(TILES / 32, 4);                 // 1568 x 4
    k_in<<<gi, 256, 65536>>>(x);
    dim3 gg(TILES / 64, 16);                // 784 x 16
    k_gemm<<<gg, 256, GEMM_SMEM>>>();
    k_out<<<(OD * TILES) / 256, 256>>>(bias, y);
}

// round 4
// speedup vs baseline: 1.3785x; 1.1105x over previous
#include <cuda_runtime.h>
#include <cuda_bf16.h>
#include <cstdint>

// Winograd F(2x2,3x3): N=16, C=128, O=128, H=W=112, pad=1
#define NB 16
#define CD 128
#define OD 128
#define HH 112
#define NT 56
#define TPI (NT*NT)            // 3136 tiles per image
#define TILES (NB*TPI)         // 50176 total tiles

// Scratch (allocation-free): U/V as bf16 hi|lo. No M scratch — fused epilogue.
__device__ unsigned short g_Ub[16 * OD * 256];            //  1 MB  U[p][o][c_hi|c_lo]
__device__ unsigned short g_Vb[(size_t)16 * TILES * 256]; // 411 MB V[p][tile][c_hi|c_lo]

__device__ __forceinline__ uint32_t smem_to_u32(const void* p) {
    uint32_t a;
    asm("{ .reg .u64 t; cvta.to.shared.u64 t, %1; cvt.u32.u64 %0, t; }" : "=r"(a) : "l"(p));
    return a;
}

// ldmatrix x4 (sm_75+)
#define LDSM4(r, addr) \
    asm volatile("ldmatrix.sync.aligned.m8n8.x4.shared.b16 {%0,%1,%2,%3}, [%4];" \
        : "=r"((r)[0]), "=r"((r)[1]), "=r"((r)[2]), "=r"((r)[3]) : "r"(addr))

// bf16 HMMA (sm_80+)
#define MMA_BF16(d, a, b) \
    asm volatile("mma.sync.aligned.m16n8k16.row.col.f32.bf16.bf16.f32 " \
        "{%0,%1,%2,%3},{%4,%5,%6,%7},{%8,%9},{%0,%1,%2,%3};" \
        : "+f"((d)[0]), "+f"((d)[1]), "+f"((d)[2]), "+f"((d)[3]) \
        : "r"((a)[0]), "r"((a)[1]), "r"((a)[2]), "r"((a)[3]), \
          "r"((b)[0]), "r"((b)[1]))

// cp.async (sm_80+)
#define CP16(dst, src) \
    asm volatile("cp.async.cg.shared.global [%0], [%1], 16;" :: "r"(dst), "l"(src) : "memory")
#define CP_COMMIT() asm volatile("cp.async.commit_group;" ::: "memory")
#define CP_WAIT0()  asm volatile("cp.async.wait_group 0;" ::: "memory")

__device__ __forceinline__ uint32_t split_pack(float v) {
    __nv_bfloat16 h = __float2bfloat16(v);
    float hf = __bfloat162float(h);
    __nv_bfloat16 l = __float2bfloat16(v - hf);
    uint16_t hu = __bfloat16_as_ushort(h);
    uint16_t lu = __bfloat16_as_ushort(l);
    return (uint32_t)hu | ((uint32_t)lu << 16);
}

// SMEM 512B-row swizzle: 32x 16B units/row; keeps bits[4:3], XORs low3 with row
__device__ __forceinline__ uint32_t swz(uint32_t u, uint32_t row) {
    return (u & 24u) | ((u ^ row) & 7u);
}

// ---------------- K1: weight transform  U = G g G^T -> bf16 hi|lo ------------
__global__ void k_wt(const float* __restrict__ w) {
    int tid = blockIdx.x * 128 + threadIdx.x;   // 16384 threads: (c,o)
    int o = tid & 127;
    int c = tid >> 7;
    const float* g = w + ((size_t)o * CD + c) * 9;
    float gm[3][3];
#pragma unroll
    for (int i = 0; i < 3; i++)
#pragma unroll
        for (int j = 0; j < 3; j++) gm[i][j] = g[i * 3 + j];

    float t[4][3];
#pragma unroll
    for (int k = 0; k < 3; k++) {
        t[0][k] = gm[0][k];
        t[1][k] = 0.5f * (gm[0][k] + gm[1][k] + gm[2][k]);
        t[2][k] = 0.5f * (gm[0][k] - gm[1][k] + gm[2][k]);
        t[3][k] = gm[2][k];
    }
#pragma unroll
    for (int i = 0; i < 4; i++) {
        float u[4];
        u[0] = t[i][0];
        u[1] = 0.5f * (t[i][0] + t[i][1] + t[i][2]);
        u[2] = 0.5f * (t[i][0] - t[i][1] + t[i][2]);
        u[3] = t[i][2];
#pragma unroll
        for (int j = 0; j < 4; j++) {
            int p = i * 4 + j;
            uint32_t hl = split_pack(u[j]);
            unsigned short* up = g_Ub + ((size_t)(p * OD + o)) * 256;
            up[c] = (unsigned short)(hl & 0xffff);
            up[128 + c] = (unsigned short)(hl >> 16);
        }
    }
}

// ---------------- K2: input transform -> V[p][tile][c_hi|c_lo] bf16 ----------
__global__ void __launch_bounds__(256) k_in(const float* __restrict__ x) {
    extern __shared__ uint32_t S[];   // [32 c][16 p][32 tiles] = 64KB
    const int tid = threadIdx.x;
    const int lane = tid & 31;
    const int cg8 = tid >> 5;

    {
        int tile = blockIdx.x * 32 + lane;
        int n = tile / TPI;
        int r = tile - n * TPI;
        int ty = r / NT;
        int tx = r - ty * NT;
        int r0 = 2 * ty - 1, c0 = 2 * tx - 1;
        const float* xn = x + (size_t)n * CD * (HH * HH);

#pragma unroll
        for (int cs = 0; cs < 4; cs++) {
            int cl = cg8 * 4 + cs;
            int c = blockIdx.y * 32 + cl;
            const float* xp = xn + (size_t)c * (HH * HH);
            float d[4][4];
#pragma unroll
            for (int ii = 0; ii < 4; ii++) {
                int rr = r0 + ii;
                bool okr = ((unsigned)rr < HH);
#pragma unroll
                for (int jj = 0; jj < 4; jj++) {
                    int cc = c0 + jj;
                    d[ii][jj] = (okr && (unsigned)cc < HH) ? xp[rr * HH + cc] : 0.0f;
                }
            }
            float t[4][4];
#pragma unroll
            for (int j = 0; j < 4; j++) {
                t[0][j] = d[0][j] - d[2][j];
                t[1][j] = d[1][j] + d[2][j];
                t[2][j] = d[2][j] - d[1][j];
                t[3][j] = d[1][j] - d[3][j];
            }
#pragma unroll
            for (int i = 0; i < 4; i++) {
                float v0 = t[i][0] - t[i][2];
                float v1 = t[i][1] + t[i][2];
                float v2 = t[i][2] - t[i][1];
                float v3 = t[i][1] - t[i][3];
                S[(cl * 16 + (i * 4 + 0)) * 32 + lane] = split_pack(v0);
                S[(cl * 16 + (i * 4 + 1)) * 32 + lane] = split_pack(v1);
                S[(cl * 16 + (i * 4 + 2)) * 32 + lane] = split_pack(v2);
                S[(cl * 16 + (i * 4 + 3)) * 32 + lane] = split_pack(v3);
            }
        }
    }
    __syncthreads();

#pragma unroll
    for (int it = 0; it < 2; it++) {
        int q = it * 256 + tid;      // 512 = 16p * 32tiles
        int p = q >> 5;
        int tl = q & 31;
        int tile = blockIdx.x * 32 + tl;

        uint32_t hp[16], lp[16];
#pragma unroll
        for (int c2 = 0; c2 < 16; c2++) {
            uint32_t u0 = S[((2 * c2) * 16 + p) * 32 + tl];
            uint32_t u1 = S[((2 * c2 + 1) * 16 + p) * 32 + tl];
            hp[c2] = (u0 & 0xffffu) | (u1 << 16);
            lp[c2] = (u0 >> 16) | (u1 & 0xffff0000u);
        }
        unsigned short* vb = g_Vb + ((size_t)p * TILES + tile) * 256 + blockIdx.y * 32;
#pragma unroll
        for (int i = 0; i < 4; i++) {
            *(uint4*)(vb + i * 8) = *((uint4*)hp + i);
            *(uint4*)(vb + 128 + i * 8) = *((uint4*)lp + i);
        }
    }
}

// ---------------- K3: fused GEMM + output transform ---------------------------
// CTA: o=128 x tiles=64, loops p=0..15. Per p: M[p] = U[p]·V[p] (bf16 3-split),
// folded into Y_ab accumulators with AT coefficients {0,±1}. Double-buffered
// cp.async staging (A 64KB + B 32KB per stage).
#define STG_BYTES 98304
#define FUSE_SMEM (2 * STG_BYTES)   // 192 KB

__global__ void __launch_bounds__(256) k_fused(const float* __restrict__ bias,
                                               float* __restrict__ y) {
    extern __shared__ char sm[];
    const uint32_t base = smem_to_u32(sm);
    const int tid = threadIdx.x;
    const int lane = tid & 31;
    const int wid = tid >> 5;
    const int jb = blockIdx.x * 64;
    const int o0 = (wid & 3) * 32;
    const int n0 = (wid >> 2) * 32;

    // stage p=0 into buffer 0
    {
        const uint4* gA = (const uint4*)g_Ub;
#pragma unroll
        for (int i = 0; i < 16; i++) {
            int g = i * 256 + tid;
            uint32_t row = (uint32_t)g >> 5, u = (uint32_t)g & 31;
            CP16(base + row * 512 + swz(u, row) * 16, gA + g);
        }
        const uint4* gB = (const uint4*)(g_Vb + (size_t)jb * 256);
#pragma unroll
        for (int i = 0; i < 8; i++) {
            int g = i * 256 + tid;
            uint32_t row = (uint32_t)g >> 5, u = (uint32_t)g & 31;
            CP16(base + 65536 + row * 512 + swz(u, row) * 16, gB + g);
        }
        CP_COMMIT();
    }

    float accY[2][2][2][4][4];
#pragma unroll
    for (int a = 0; a < 2; a++)
#pragma unroll
        for (int b = 0; b < 2; b++)
#pragma unroll
            for (int m = 0; m < 2; m++)
#pragma unroll
                for (int nf = 0; nf < 4; nf++)
#pragma unroll
                    for (int j = 0; j < 4; j++) accY[a][b][m][nf][j] = 0.0f;

    const uint32_t rA = (uint32_t)(o0 + (lane & 15));
    const uint32_t uA = (uint32_t)(lane >> 4);
    const uint32_t rB = (uint32_t)(n0 + (lane & 7) + ((lane & 16) >> 1));
    const uint32_t uB = (uint32_t)((lane >> 3) & 1);

    const float AT0[4] = {1.f, 1.f, 1.f, 0.f};
    const float AT1[4] = {0.f, 1.f, -1.f, -1.f};

#pragma unroll
    for (int p = 0; p < 16; p++) {
        CP_WAIT0();
        __syncthreads();

        if (p < 15) {   // stage p+1 into the other buffer
            uint32_t nb = base + (uint32_t)((p + 1) & 1) * STG_BYTES;
            const uint4* gA = (const uint4*)(g_Ub + (size_t)(p + 1) * OD * 256);
#pragma unroll
            for (int i = 0; i < 16; i++) {
                int g = i * 256 + tid;
                uint32_t row = (uint32_t)g >> 5, u = (uint32_t)g & 31;
                CP16(nb + row * 512 + swz(u, row) * 16, gA + g);
            }
            const uint4* gB = (const uint4*)(g_Vb + ((size_t)(p + 1) * TILES + jb) * 256);
#pragma unroll
            for (int i = 0; i < 8; i++) {
                int g = i * 256 + tid;
                uint32_t row = (uint32_t)g >> 5, u = (uint32_t)g & 31;
                CP16(nb + 65536 + row * 512 + swz(u, row) * 16, gB + g);
            }
            CP_COMMIT();
        }

        const uint32_t aB = base + (uint32_t)(p & 1) * STG_BYTES;
        const uint32_t bB = aB + 65536;

        float macc[2][4][4];
#pragma unroll
        for (int m = 0; m < 2; m++)
#pragma unroll
            for (int nf = 0; nf < 4; nf++)
#pragma unroll
                for (int j = 0; j < 4; j++) macc[m][nf][j] = 0.0f;

#pragma unroll 1
        for (int kc = 0; kc < 8; kc++) {
            uint32_t ah[2][4], al[2][4], bh[4][2], bl[4][2];
#pragma unroll
            for (int m = 0; m < 2; m++) {
                uint32_t r = rA + m * 16;
                uint32_t u = 2 * kc + uA;
                LDSM4(ah[m], aB + r * 512 + (swz(u, r) << 4));
                u += 16;
                LDSM4(al[m], aB + r * 512 + (swz(u, r) << 4));
            }
#pragma unroll
            for (int q = 0; q < 2; q++) {
                uint32_t r = rB + q * 16;
                uint32_t u = 2 * kc + uB;
                uint32_t t[4];
                LDSM4(t, bB + r * 512 + (swz(u, r) << 4));
                bh[2 * q][0] = t[0]; bh[2 * q][1] = t[1];
                bh[2 * q + 1][0] = t[2]; bh[2 * q + 1][1] = t[3];
                u += 16;
                LDSM4(t, bB + r * 512 + (swz(u, r) << 4));
                bl[2 * q][0] = t[0]; bl[2 * q][1] = t[1];
                bl[2 * q + 1][0] = t[2]; bl[2 * q + 1][1] = t[3];
            }
#pragma unroll
            for (int m = 0; m < 2; m++)
#pragma unroll
                for (int nf = 0; nf < 4; nf++) {
                    MMA_BF16(macc[m][nf], ah[m], bh[nf]);
                    MMA_BF16(macc[m][nf], ah[m], bl[nf]);
                    MMA_BF16(macc[m][nf], al[m], bh[nf]);
                }
        }

        // fold M[p] into Y_ab with compile-time ±1 coefficients (p fully unrolled)
        const int pi = p >> 2, pj = p & 3;
#pragma unroll
        for (int a = 0; a < 2; a++) {
            const float wa = (a == 0) ? AT0[pi] : AT1[pi];
#pragma unroll
            for (int b = 0; b < 2; b++) {
                const float wb = (b == 0) ? AT0[pj] : AT1[pj];
                const float c = wa * wb;
                if (c != 0.0f) {
#pragma unroll
                    for (int m = 0; m < 2; m++)
#pragma unroll
                        for (int nf = 0; nf < 4; nf++)
#pragma unroll
                            for (int j = 0; j < 4; j++)
                                accY[a][b][m][nf][j] += c * macc[m][nf][j];
                }
            }
        }
        __syncthreads();
    }

    // Epilogue: bias + direct Y writes (float2 over the b dimension)
#pragma unroll
    for (int m = 0; m < 2; m++) {
#pragma unroll
        for (int h = 0; h < 2; h++) {
            int o = o0 + m * 16 + (lane >> 2) + h * 8;
            float bv = bias[o];
#pragma unroll
            for (int nf = 0; nf < 4; nf++) {
#pragma unroll
                for (int d = 0; d < 2; d++) {
                    int t = jb + n0 + nf * 8 + (lane & 3) * 2 + d;
                    int n = t / TPI;
                    int r = t - n * TPI;
                    int ty = r / NT;
                    int tx = r - ty * NT;
                    float* yp = y + ((size_t)(n * OD + o) * HH + 2 * ty) * HH + 2 * tx;
                    int j = 2 * h + d;
                    float2 v0 = make_float2(accY[0][0][m][nf][j] + bv,
                                            accY[0][1][m][nf][j] + bv);
                    float2 v1 = make_float2(accY[1][0][m][nf][j] + bv,
                                            accY[1][1][m][nf][j] + bv);
                    *(float2*)yp = v0;
                    *(float2*)(yp + HH) = v1;
                }
            }
        }
    }
}

// ---------------- launch --------------------------------------------------------
extern "C" void kernel_launch(void* const* d_in, const int* in_sizes, int n_in,
                              void* d_out, int out_size) {
    const float* x = (const float*)d_in[0];
    const float* w = (const float*)d_in[1];
    const float* bias = (const float*)d_in[2];
    float* y = (float*)d_out;

    cudaFuncSetAttribute(k_in, cudaFuncAttributeMaxDynamicSharedMemorySize, 65536);
    cudaFuncSetAttribute(k_fused, cudaFuncAttributeMaxDynamicSharedMemorySize, FUSE_SMEM);

    k_wt<<<128, 128>>>(w);
    dim3 gi(TILES / 32, 4);                 // 1568 x 4
    k_in<<<gi, 256, 65536>>>(x);
    k_fused<<<TILES / 64, 256, FUSE_SMEM>>>(bias, y);   // 784 CTAs
}